// round 12
// baseline (speedup 1.0000x reference)
#include <cuda_runtime.h>

// ShiftWindowMSA fused kernel for GB300 (sm_103a) — round 10:
// warp-column-split GEMMs (each warp owns a column slice; weight tile read once
// per owning warp, not by all warps) + col-major weight tiles with
// conflict-free staging. 256 threads, 2 CTA/SM. Numerics identical to R3.

#define NTOK    49
#define CH      96
#define NH      3
#define HD      32
#define RS      100         // activation row stride (16B-aligned rows)
#define WTS     36          // weight tile stride: wt[col][cc], 36 = mult4, banks 4 apart
#define ATS     52          // attn row stride
#define HP      224
#define THREADS 256

// smem float offsets
#define OA 0                // X -> K -> AV result       (49*100 = 4900)
#define OB 4900             // SX -> Q -> proj wt tile   (4900)
#define OC 9800             // V                         (4900)
#define OD 14700            // KV/Q wt tiles -> attn     (7644)
#define OE 22344            // rel-pos bias table        (507)
#define SMEM_FLOATS 22932   // incl. junk-row read padding
#define SMEM_BYTES  (SMEM_FLOATS * 4)

typedef unsigned long long u64;

__device__ __forceinline__ u64 pk2(float lo, float hi) {
    u64 r; asm("mov.b64 %0, {%1, %2};" : "=l"(r) : "f"(lo), "f"(hi)); return r;
}
__device__ __forceinline__ void upk2(u64 v, float& lo, float& hi) {
    asm("mov.b64 {%0, %1}, %2;" : "=f"(lo), "=f"(hi) : "l"(v));
}
__device__ __forceinline__ void ffma2(u64& d, u64 a, u64 b) {
    asm("fma.rn.f32x2 %0, %1, %2, %0;" : "+l"(d) : "l"(a), "l"(b));
}
__device__ __forceinline__ float comp(const float4& v, int q) {
    return (q == 0) ? v.x : (q == 1) ? v.y : (q == 2) ? v.z : v.w;
}

__global__ __launch_bounds__(THREADS, 2)
void swin_msa_kernel(const float* __restrict__ query,
                     const float* __restrict__ skipq,
                     const float* __restrict__ qkv_w,
                     const float* __restrict__ qkv_b,
                     const float* __restrict__ skip_w,
                     const float* __restrict__ skip_b,
                     const float* __restrict__ proj_w,
                     const float* __restrict__ proj_b,
                     const float* __restrict__ btab,
                     float* __restrict__ out)
{
    extern __shared__ float sm[];
    __shared__ int fval[NTOK];
    __shared__ int regid[NTOK];
    __shared__ int rowoff[NTOK];

    const int t   = threadIdx.x;
    const int blk = blockIdx.x;
    const int b   = blk >> 10;
    const int wi  = blk & 1023;
    const int wr  = wi >> 5;
    const int wc  = wi & 31;

    if (t < NTOK) {
        int r = t / 7, c = t - r * 7;
        fval[t] = 13 * r + c;
        int hg = wr * 7 + r;
        int wg = wc * 7 + c;
        int rh = (hg < 217) ? 0 : ((hg < 221) ? 1 : 2);
        int rw = (wg < 217) ? 0 : ((wg < 221) ? 1 : 2);
        regid[t] = rh * 3 + rw;
        int hs = hg + 3; if (hs >= HP) hs -= HP;
        int ws = wg + 3; if (ws >= HP) ws -= HP;
        rowoff[t] = (b * (HP * HP) + hs * HP + ws) * CH;
    }
    for (int i = t; i < 507; i += THREADS) sm[OE + i] = btab[i];
    __syncthreads();

    // ---- load x -> A, sx -> B ----
    {
        const int warp = t >> 5, lane = t & 31;
        for (int n = warp; n < NTOK; n += 8) {
            if (lane < 24) {
                const int base = rowoff[n];
                float4 xv = *(const float4*)(query + base + lane * 4);
                float4 sv = *(const float4*)(skipq + base + lane * 4);
                *(float4*)&sm[OA + n * RS + lane * 4] = xv;
                *(float4*)&sm[OB + n * RS + lane * 4] = sv;
            }
        }
    }

    const int tj = t & 31;      // lane
    const int w  = t >> 5;      // warp (8)
    const int cg = tj & 3;      // col group within warp slice
    const int rh = tj >> 2;     // row group: rows rh + 8*i, i < 7

    // ================= KV GEMM: warp owns cols [24w, 24w+24) ==================
    // lane owns cols {24w + cg + 4p : p=0..5}; FMA2 pairs (cg+8g, cg+8g+4).
    {
        const int cb = 24 * w + cg;
        u64 acc2[7][3];
        #pragma unroll
        for (int g = 0; g < 3; ++g) {
            u64 b2 = pk2(qkv_b[cb + 8 * g], qkv_b[cb + 8 * g + 4]);
            #pragma unroll
            for (int i = 0; i < 7; ++i) acc2[i][g] = b2;
        }
        for (int ch = 0; ch < 3; ++ch) {
            __syncthreads();
            // stage col-major tile: wt[col][cc]; coalesced LDG, conflict-free STS
            for (int i2 = t; i2 < 192 * 32; i2 += THREADS) {
                const int col = i2 >> 5, cc = i2 & 31;
                sm[OD + col * WTS + cc] = qkv_w[col * CH + ch * 32 + cc];
            }
            __syncthreads();
            #pragma unroll 2
            for (int cq = 0; cq < 8; ++cq) {
                float4 a4[7];
                #pragma unroll
                for (int i = 0; i < 7; ++i)
                    a4[i] = *(const float4*)&sm[OA + (rh + 8 * i) * RS + ch * 32 + cq * 4];
                float4 wf[6];
                #pragma unroll
                for (int p = 0; p < 6; ++p)
                    wf[p] = *(const float4*)&sm[OD + (cb + 4 * p) * WTS + cq * 4];
                #pragma unroll
                for (int q = 0; q < 4; ++q) {
                    u64 wp[3];
                    #pragma unroll
                    for (int g = 0; g < 3; ++g)
                        wp[g] = pk2(comp(wf[2 * g], q), comp(wf[2 * g + 1], q));
                    #pragma unroll
                    for (int i = 0; i < 7; ++i) {
                        const float av = comp(a4[i], q);
                        const u64 a2 = pk2(av, av);
                        ffma2(acc2[i][0], a2, wp[0]);
                        ffma2(acc2[i][1], a2, wp[1]);
                        ffma2(acc2[i][2], a2, wp[2]);
                    }
                }
            }
        }
        __syncthreads();
        // warps 0-3 -> K (cols 0..95) into OA ; warps 4-7 -> V into OC
        const int dbase = (w < 4) ? OA : OC;
        const int coff  = (w < 4) ? cb : (cb - 96);
        #pragma unroll
        for (int i = 0; i < 7; ++i) {
            const int n = rh + 8 * i;
            if (n < NTOK) {
                #pragma unroll
                for (int g = 0; g < 3; ++g) {
                    float lo, hi; upk2(acc2[i][g], lo, hi);
                    sm[dbase + n * RS + coff + 8 * g]     = lo;
                    sm[dbase + n * RS + coff + 8 * g + 4] = hi;
                }
            }
        }
    }

    // ================= Q GEMM: warp owns cols [12w, 12w+12) ====================
    // lane owns cols {12w + cg + 4p : p=0..2}; pair (cg, cg+4), scalar cg+8.
    {
        const int cq0 = 12 * w + cg;
        u64 accp[7]; float accs[7];
        {
            u64 b2 = pk2(skip_b[cq0], skip_b[cq0 + 4]);
            const float bs = skip_b[cq0 + 8];
            #pragma unroll
            for (int i = 0; i < 7; ++i) { accp[i] = b2; accs[i] = bs; }
        }
        for (int ch = 0; ch < 3; ++ch) {
            __syncthreads();
            for (int i2 = t; i2 < 96 * 32; i2 += THREADS) {
                const int col = i2 >> 5, cc = i2 & 31;
                sm[OD + col * WTS + cc] = skip_w[col * CH + ch * 32 + cc];
            }
            __syncthreads();
            #pragma unroll 2
            for (int cqi = 0; cqi < 8; ++cqi) {
                float4 a4[7];
                #pragma unroll
                for (int i = 0; i < 7; ++i)
                    a4[i] = *(const float4*)&sm[OB + (rh + 8 * i) * RS + ch * 32 + cqi * 4];
                float4 wf[3];
                #pragma unroll
                for (int p = 0; p < 3; ++p)
                    wf[p] = *(const float4*)&sm[OD + (cq0 + 4 * p) * WTS + cqi * 4];
                #pragma unroll
                for (int q = 0; q < 4; ++q) {
                    const u64 wpp = pk2(comp(wf[0], q), comp(wf[1], q));
                    const float wsv = comp(wf[2], q);
                    #pragma unroll
                    for (int i = 0; i < 7; ++i) {
                        const float av = comp(a4[i], q);
                        ffma2(accp[i], pk2(av, av), wpp);
                        accs[i] += av * wsv;
                    }
                }
            }
        }
        __syncthreads();
        #pragma unroll
        for (int i = 0; i < 7; ++i) {
            const int n = rh + 8 * i;
            if (n < NTOK) {
                float lo, hi; upk2(accp[i], lo, hi);
                sm[OB + n * RS + cq0]     = lo;
                sm[OB + n * RS + cq0 + 4] = hi;
                sm[OB + n * RS + cq0 + 8] = accs[i];
            }
        }
    }
    __syncthreads();

    // ================= QK^T + bias + mask -> attn in OD =================
    const float scale = 0.17677669529663687f;
    if (t < NH * NTOK) {
        const int h  = t / NTOK;
        const int r  = t - h * NTOK;
        const int rn = r / 7;
        const int rm = r - rn * 7;
        float s[7][7];
        #pragma unroll
        for (int i = 0; i < 7; ++i)
            #pragma unroll
            for (int j = 0; j < 7; ++j) s[i][j] = 0.f;
        const float* qb = sm + OB + rn * RS + h * HD;
        const float* kb = sm + OA + rm * RS + h * HD;
        #pragma unroll
        for (int kq = 0; kq < 8; ++kq) {
            float4 k4[7];
            #pragma unroll
            for (int j = 0; j < 7; ++j) k4[j] = *(const float4*)(kb + j * 7 * RS + kq * 4);
            #pragma unroll
            for (int i = 0; i < 7; ++i) {
                float4 q4 = *(const float4*)(qb + i * 7 * RS + kq * 4);
                #pragma unroll
                for (int j = 0; j < 7; ++j)
                    s[i][j] += q4.x * k4[j].x + q4.y * k4[j].y + q4.z * k4[j].z + q4.w * k4[j].w;
            }
        }
        #pragma unroll
        for (int i = 0; i < 7; ++i) {
            const int n = rn + 7 * i;
            #pragma unroll
            for (int j = 0; j < 7; ++j) {
                const int m = rm + 7 * j;
                const float bias = sm[OE + (fval[n] + fval[48 - m]) * 3 + h];
                const float mask = (regid[n] != regid[m]) ? -100.f : 0.f;
                sm[OD + h * (NTOK * ATS) + n * ATS + m] = s[i][j] * scale + bias + mask;
            }
        }
    }
    __syncthreads();

    // ================= softmax =================
    if (t < NH * NTOK) {
        float* row = sm + OD + (t / NTOK) * (NTOK * ATS) + (t % NTOK) * ATS;
        float rv[49];
        #pragma unroll
        for (int q = 0; q < 12; ++q) {
            float4 v = *(const float4*)(row + 4 * q);
            rv[4 * q] = v.x; rv[4 * q + 1] = v.y; rv[4 * q + 2] = v.z; rv[4 * q + 3] = v.w;
        }
        rv[48] = row[48];
        float mx = rv[0];
        #pragma unroll
        for (int i = 1; i < 49; ++i) mx = fmaxf(mx, rv[i]);
        float ssum = 0.f;
        #pragma unroll
        for (int i = 0; i < 49; ++i) { rv[i] = __expf(rv[i] - mx); ssum += rv[i]; }
        const float inv = 1.f / ssum;
        #pragma unroll
        for (int q = 0; q < 12; ++q)
            *(float4*)(row + 4 * q) = make_float4(rv[4*q] * inv, rv[4*q+1] * inv,
                                                 rv[4*q+2] * inv, rv[4*q+3] * inv);
        row[48] = rv[48] * inv;
    }
    __syncthreads();

    // ================= AV: dual-accumulator f32x2 over m (7-row tiles) ==========
    {
        u64 acc2[7][3];
        #pragma unroll
        for (int i = 0; i < 7; ++i)
            #pragma unroll
            for (int h = 0; h < 3; ++h) acc2[i][h] = pk2(0.f, 0.f);
        #pragma unroll 2
        for (int mq = 0; mq < 12; ++mq) {
            const int m0 = 4 * mq;
            u64 va[3], vb[3];
            #pragma unroll
            for (int h = 0; h < 3; ++h) {
                const int vc = h * HD + tj;
                va[h] = pk2(sm[OC + m0 * RS + vc],       sm[OC + (m0 + 1) * RS + vc]);
                vb[h] = pk2(sm[OC + (m0 + 2) * RS + vc], sm[OC + (m0 + 3) * RS + vc]);
            }
            #pragma unroll
            for (int i = 0; i < 7; ++i) {
                const int n = w + 8 * i;
                #pragma unroll
                for (int h = 0; h < 3; ++h) {
                    float4 a4 = *(const float4*)&sm[OD + h * (NTOK * ATS) + n * ATS + m0];
                    ffma2(acc2[i][h], pk2(a4.x, a4.y), va[h]);
                    ffma2(acc2[i][h], pk2(a4.z, a4.w), vb[h]);
                }
            }
        }
        {   // tail m = 48
            float vt[3];
            #pragma unroll
            for (int h = 0; h < 3; ++h) vt[h] = sm[OC + 48 * RS + h * HD + tj];
            #pragma unroll
            for (int i = 0; i < 7; ++i) {
                const int n = w + 8 * i;
                #pragma unroll
                for (int h = 0; h < 3; ++h) {
                    const float at = sm[OD + h * (NTOK * ATS) + n * ATS + 48];
                    ffma2(acc2[i][h], pk2(at, 0.f), pk2(vt[h], 0.f));
                }
            }
        }
        __syncthreads();
        #pragma unroll
        for (int i = 0; i < 7; ++i) {
            const int n = w + 8 * i;
            if (n < NTOK) {
                #pragma unroll
                for (int h = 0; h < 3; ++h) {
                    float lo, hi; upk2(acc2[i][h], lo, hi);
                    sm[OA + n * RS + h * HD + tj] = lo + hi;
                }
            }
        }
    }

    // ================= proj GEMM: col-split like Q; input OA; tile in OB ========
    {
        const int cq0 = 12 * w + cg;
        u64 accp[7]; float accs[7];
        {
            u64 b2 = pk2(proj_b[cq0], proj_b[cq0 + 4]);
            const float bs = proj_b[cq0 + 8];
            #pragma unroll
            for (int i = 0; i < 7; ++i) { accp[i] = b2; accs[i] = bs; }
        }
        for (int ch = 0; ch < 3; ++ch) {
            __syncthreads();
            for (int i2 = t; i2 < 96 * 32; i2 += THREADS) {
                const int col = i2 >> 5, cc = i2 & 31;
                sm[OB + col * WTS + cc] = proj_w[col * CH + ch * 32 + cc];
            }
            __syncthreads();
            #pragma unroll 2
            for (int cqi = 0; cqi < 8; ++cqi) {
                float4 a4[7];
                #pragma unroll
                for (int i = 0; i < 7; ++i)
                    a4[i] = *(const float4*)&sm[OA + (rh + 8 * i) * RS + ch * 32 + cqi * 4];
                float4 wf[3];
                #pragma unroll
                for (int p = 0; p < 3; ++p)
                    wf[p] = *(const float4*)&sm[OB + (cq0 + 4 * p) * WTS + cqi * 4];
                #pragma unroll
                for (int q = 0; q < 4; ++q) {
                    const u64 wpp = pk2(comp(wf[0], q), comp(wf[1], q));
                    const float wsv = comp(wf[2], q);
                    #pragma unroll
                    for (int i = 0; i < 7; ++i) {
                        const float av = comp(a4[i], q);
                        ffma2(accp[i], pk2(av, av), wpp);
                        accs[i] += av * wsv;
                    }
                }
            }
        }
        #pragma unroll
        for (int i = 0; i < 7; ++i) {
            const int n = rh + 8 * i;
            if (n < NTOK) {
                float lo, hi; upk2(accp[i], lo, hi);
                out[rowoff[n] + cq0]     = lo;
                out[rowoff[n] + cq0 + 4] = hi;
                out[rowoff[n] + cq0 + 8] = accs[i];
            }
        }
    }
}

extern "C" void kernel_launch(void* const* d_in, const int* in_sizes, int n_in,
                              void* d_out, int out_size)
{
    (void)in_sizes; (void)n_in; (void)out_size;
    const float* query  = (const float*)d_in[0];
    const float* skipq  = (const float*)d_in[1];
    const float* qkv_w  = (const float*)d_in[2];
    const float* qkv_b  = (const float*)d_in[3];
    const float* skip_w = (const float*)d_in[4];
    const float* skip_b = (const float*)d_in[5];
    const float* proj_w = (const float*)d_in[6];
    const float* proj_b = (const float*)d_in[7];
    const float* btab   = (const float*)d_in[8];
    float* out = (float*)d_out;

    cudaFuncSetAttribute(swin_msa_kernel,
                         cudaFuncAttributeMaxDynamicSharedMemorySize, SMEM_BYTES);

    swin_msa_kernel<<<4 * 1024, THREADS, SMEM_BYTES>>>(
        query, skipq, qkv_w, qkv_b, skip_w, skip_b, proj_w, proj_b, btab, out);
}

// round 13
// speedup vs baseline: 1.2870x; 1.2870x over previous
#include <cuda_runtime.h>

// ShiftWindowMSA fused kernel for GB300 (sm_103a) — round 13:
// R3 compute structure (best: 656us) + double-buffered (ping-pong) weight
// staging: chunk ch+1 is staged while chunk ch is computed; 1 sync per chunk
// instead of 2; LDG(L2) latency hidden behind FFMA2 work.
// Numerics identical to R3.

#define NTOK    49
#define CH      96
#define NH      3
#define HD      32
#define RS      100         // activation row stride (16B-aligned rows)
#define KWS     202         // KV weight tile row stride (cc-major [32][192+10])
#define QWS     106         // Q/proj weight tile row stride (cc-major [32][96+10])
#define ATS     52          // attn row stride
#define HP      224
#define THREADS 256

#define KVB     (32 * KWS)  // 6464 floats: one KV weight chunk buffer
#define QB      (32 * QWS)  // 3392 floats: one Q/proj weight chunk buffer

// smem float offsets
#define OA 0                // X -> K -> AV result       (49*100 = 4900)
#define OB 4900             // SX -> Q                   (4900)
#define OC 9800             // V                         (4900)
#define OD 14700            // weight ping-pong buffers (2*6464) / attn (3*49*52+pad)
#define OE 27628            // rel-pos bias table        (507)
#define SMEM_FLOATS 28135
#define SMEM_BYTES  (SMEM_FLOATS * 4)

typedef unsigned long long u64;

__device__ __forceinline__ u64 pk2(float lo, float hi) {
    u64 r; asm("mov.b64 %0, {%1, %2};" : "=l"(r) : "f"(lo), "f"(hi)); return r;
}
__device__ __forceinline__ void upk2(u64 v, float& lo, float& hi) {
    asm("mov.b64 {%0, %1}, %2;" : "=f"(lo), "=f"(hi) : "l"(v));
}
__device__ __forceinline__ void ffma2(u64& d, u64 a, u64 b) {
    asm("fma.rn.f32x2 %0, %1, %2, %0;" : "+l"(d) : "l"(a), "l"(b));
}

__global__ __launch_bounds__(THREADS, 2)
void swin_msa_kernel(const float* __restrict__ query,
                     const float* __restrict__ skipq,
                     const float* __restrict__ qkv_w,
                     const float* __restrict__ qkv_b,
                     const float* __restrict__ skip_w,
                     const float* __restrict__ skip_b,
                     const float* __restrict__ proj_w,
                     const float* __restrict__ proj_b,
                     const float* __restrict__ btab,
                     float* __restrict__ out)
{
    extern __shared__ float sm[];
    __shared__ int fval[NTOK];
    __shared__ int regid[NTOK];
    __shared__ int rowoff[NTOK];

    const int t   = threadIdx.x;
    const int blk = blockIdx.x;
    const int b   = blk >> 10;
    const int wi  = blk & 1023;
    const int wr  = wi >> 5;
    const int wc  = wi & 31;

    if (t < NTOK) {
        int r = t / 7, c = t - r * 7;
        fval[t] = 13 * r + c;
        int hg = wr * 7 + r;
        int wg = wc * 7 + c;
        int rh = (hg < 217) ? 0 : ((hg < 221) ? 1 : 2);
        int rw = (wg < 217) ? 0 : ((wg < 221) ? 1 : 2);
        regid[t] = rh * 3 + rw;
        int hs = hg + 3; if (hs >= HP) hs -= HP;
        int ws = wg + 3; if (ws >= HP) ws -= HP;
        rowoff[t] = (b * (HP * HP) + hs * HP + ws) * CH;
    }
    for (int i = t; i < 507; i += THREADS) sm[OE + i] = btab[i];
    __syncthreads();

    // ---- load x -> A, sx -> B ; prestage KV weight chunk 0 -> OD buf0 ----
    {
        const int warp = t >> 5, lane = t & 31;
        for (int n = warp; n < NTOK; n += 8) {
            if (lane < 24) {
                const int base = rowoff[n];
                float4 xv = *(const float4*)(query + base + lane * 4);
                float4 sv = *(const float4*)(skipq + base + lane * 4);
                *(float4*)&sm[OA + n * RS + lane * 4] = xv;
                *(float4*)&sm[OB + n * RS + lane * 4] = sv;
            }
        }
        for (int i2 = t; i2 < 192 * 32; i2 += THREADS) {
            const int j = i2 >> 5, cc = i2 & 31;
            sm[OD + cc * KWS + j] = qkv_w[j * CH + cc];
        }
    }
    __syncthreads();

    const int tj = t & 31;
    const int tn = t >> 5;

    // ================= KV GEMM: 49x192, tile 7 rows x 3 col-pairs ==============
    {
        u64 acc2[7][3];
        #pragma unroll
        for (int g = 0; g < 3; ++g) {
            const int col = 2 * tj + 64 * g;
            u64 b2 = pk2(qkv_b[col], qkv_b[col + 1]);
            #pragma unroll
            for (int i = 0; i < 7; ++i) acc2[i][g] = b2;
        }
        for (int ch = 0; ch < 3; ++ch) {
            // stage next chunk into other buffer (overlaps with compute below)
            if (ch < 2) {
                const int nb = OD + ((ch + 1) & 1) * KVB;
                for (int i2 = t; i2 < 192 * 32; i2 += THREADS) {
                    const int j = i2 >> 5, cc = i2 & 31;
                    sm[nb + cc * KWS + j] = qkv_w[j * CH + (ch + 1) * 32 + cc];
                }
            }
            const int cb = OD + (ch & 1) * KVB;
            #pragma unroll 2
            for (int cq = 0; cq < 8; ++cq) {
                float4 a4[7];
                #pragma unroll
                for (int i = 0; i < 7; ++i)
                    a4[i] = *(const float4*)&sm[OA + (tn + 8 * i) * RS + ch * 32 + cq * 4];
                const float* wb = sm + cb + (cq * 4) * KWS + 2 * tj;
                #pragma unroll
                for (int q = 0; q < 4; ++q) {
                    u64 w0 = *(const u64*)(wb + q * KWS);
                    u64 w1 = *(const u64*)(wb + q * KWS + 64);
                    u64 w2 = *(const u64*)(wb + q * KWS + 128);
                    #pragma unroll
                    for (int i = 0; i < 7; ++i) {
                        const float av = (q == 0) ? a4[i].x : (q == 1) ? a4[i].y
                                       : (q == 2) ? a4[i].z : a4[i].w;
                        const u64 a2 = pk2(av, av);
                        ffma2(acc2[i][0], a2, w0);
                        ffma2(acc2[i][1], a2, w1);
                        ffma2(acc2[i][2], a2, w2);
                    }
                }
            }
            __syncthreads();
        }
        // K (cols 0..95) overwrites X in A ; V -> C   (all X reads done: sync above)
        #pragma unroll
        for (int i = 0; i < 7; ++i) {
            const int n = tn + 8 * i;
            if (n < NTOK) {
                #pragma unroll
                for (int g = 0; g < 3; ++g) {
                    const int col = 2 * tj + 64 * g;
                    float lo, hi; upk2(acc2[i][g], lo, hi);
                    if (col < 96) *(float2*)&sm[OA + n * RS + col] = make_float2(lo, hi);
                    else          *(float2*)&sm[OC + n * RS + col - 96] = make_float2(lo, hi);
                }
            }
        }
    }

    // ---- prestage Q weight chunk 0 -> OD buf0 (buf0 free: last KV read was ch2=buf0,
    //      synced at KV loop end; concurrent with K/V result stores above) ----
    for (int i2 = t; i2 < 96 * 32; i2 += THREADS) {
        const int j = i2 >> 5, cc = i2 & 31;
        sm[OD + cc * QWS + j] = skip_w[j * CH + cc];
    }
    __syncthreads();

    // ================= Q GEMM: 49x96, cols {2tj,2tj+1} pair + {64+tj} ==========
    {
        u64 accp[7]; float accs[7];
        {
            u64 b2 = pk2(skip_b[2 * tj], skip_b[2 * tj + 1]);
            const float bs = skip_b[64 + tj];
            #pragma unroll
            for (int i = 0; i < 7; ++i) { accp[i] = b2; accs[i] = bs; }
        }
        for (int ch = 0; ch < 3; ++ch) {
            if (ch < 2) {
                const int nb = OD + ((ch + 1) & 1) * QB;
                for (int i2 = t; i2 < 96 * 32; i2 += THREADS) {
                    const int j = i2 >> 5, cc = i2 & 31;
                    sm[nb + cc * QWS + j] = skip_w[j * CH + (ch + 1) * 32 + cc];
                }
            }
            const int cb = OD + (ch & 1) * QB;
            #pragma unroll 2
            for (int cq = 0; cq < 8; ++cq) {
                float4 a4[7];
                #pragma unroll
                for (int i = 0; i < 7; ++i)
                    a4[i] = *(const float4*)&sm[OB + (tn + 8 * i) * RS + ch * 32 + cq * 4];
                const float* wb = sm + cb + (cq * 4) * QWS;
                #pragma unroll
                for (int q = 0; q < 4; ++q) {
                    u64 w2 = *(const u64*)(wb + q * QWS + 2 * tj);
                    float ws = wb[q * QWS + 64 + tj];
                    #pragma unroll
                    for (int i = 0; i < 7; ++i) {
                        const float av = (q == 0) ? a4[i].x : (q == 1) ? a4[i].y
                                       : (q == 2) ? a4[i].z : a4[i].w;
                        ffma2(accp[i], pk2(av, av), w2);
                        accs[i] += av * ws;
                    }
                }
            }
            __syncthreads();
        }
        // Q overwrites SX in B (all SX reads done: sync above)
        #pragma unroll
        for (int i = 0; i < 7; ++i) {
            const int n = tn + 8 * i;
            if (n < NTOK) {
                float lo, hi; upk2(accp[i], lo, hi);
                *(float2*)&sm[OB + n * RS + 2 * tj] = make_float2(lo, hi);
                sm[OB + n * RS + 64 + tj] = accs[i];
            }
        }
    }
    __syncthreads();

    // ================= QK^T + bias + mask -> attn (stride ATS) =================
    const float scale = 0.17677669529663687f;
    if (t < NH * NTOK) {
        const int h  = t / NTOK;
        const int r  = t - h * NTOK;
        const int rn = r / 7;
        const int rm = r - rn * 7;
        float s[7][7];
        #pragma unroll
        for (int i = 0; i < 7; ++i)
            #pragma unroll
            for (int j = 0; j < 7; ++j) s[i][j] = 0.f;
        const float* qb = sm + OB + rn * RS + h * HD;
        const float* kb = sm + OA + rm * RS + h * HD;
        #pragma unroll
        for (int kq = 0; kq < 8; ++kq) {
            float4 k4[7];
            #pragma unroll
            for (int j = 0; j < 7; ++j) k4[j] = *(const float4*)(kb + j * 7 * RS + kq * 4);
            #pragma unroll
            for (int i = 0; i < 7; ++i) {
                float4 q4 = *(const float4*)(qb + i * 7 * RS + kq * 4);
                #pragma unroll
                for (int j = 0; j < 7; ++j)
                    s[i][j] += q4.x * k4[j].x + q4.y * k4[j].y + q4.z * k4[j].z + q4.w * k4[j].w;
            }
        }
        #pragma unroll
        for (int i = 0; i < 7; ++i) {
            const int n = rn + 7 * i;
            #pragma unroll
            for (int j = 0; j < 7; ++j) {
                const int m = rm + 7 * j;
                const float bias = sm[OE + (fval[n] + fval[48 - m]) * 3 + h];
                const float mask = (regid[n] != regid[m]) ? -100.f : 0.f;
                sm[OD + h * (NTOK * ATS) + n * ATS + m] = s[i][j] * scale + bias + mask;
            }
        }
    }
    __syncthreads();

    // ================= softmax =================
    if (t < NH * NTOK) {
        float* row = sm + OD + (t / NTOK) * (NTOK * ATS) + (t % NTOK) * ATS;
        float rv[49];
        #pragma unroll
        for (int q = 0; q < 12; ++q) {
            float4 v = *(const float4*)(row + 4 * q);
            rv[4 * q] = v.x; rv[4 * q + 1] = v.y; rv[4 * q + 2] = v.z; rv[4 * q + 3] = v.w;
        }
        rv[48] = row[48];
        float mx = rv[0];
        #pragma unroll
        for (int i = 1; i < 49; ++i) mx = fmaxf(mx, rv[i]);
        float ssum = 0.f;
        #pragma unroll
        for (int i = 0; i < 49; ++i) { rv[i] = __expf(rv[i] - mx); ssum += rv[i]; }
        const float inv = 1.f / ssum;
        #pragma unroll
        for (int q = 0; q < 12; ++q)
            *(float4*)(row + 4 * q) = make_float4(rv[4*q] * inv, rv[4*q+1] * inv,
                                                 rv[4*q+2] * inv, rv[4*q+3] * inv);
        row[48] = rv[48] * inv;
    }
    __syncthreads();

    // ================= AV: dual-accumulator f32x2 over m =================
    {
        u64 acc2[7][3];
        #pragma unroll
        for (int i = 0; i < 7; ++i)
            #pragma unroll
            for (int h = 0; h < 3; ++h) acc2[i][h] = pk2(0.f, 0.f);
        #pragma unroll 2
        for (int mq = 0; mq < 12; ++mq) {
            const int m0 = 4 * mq;
            u64 va[3], vb[3];
            #pragma unroll
            for (int h = 0; h < 3; ++h) {
                const int vc = h * HD + tj;
                va[h] = pk2(sm[OC + m0 * RS + vc],       sm[OC + (m0 + 1) * RS + vc]);
                vb[h] = pk2(sm[OC + (m0 + 2) * RS + vc], sm[OC + (m0 + 3) * RS + vc]);
            }
            #pragma unroll
            for (int i = 0; i < 7; ++i) {
                const int n = tn + 8 * i;
                #pragma unroll
                for (int h = 0; h < 3; ++h) {
                    float4 a4 = *(const float4*)&sm[OD + h * (NTOK * ATS) + n * ATS + m0];
                    ffma2(acc2[i][h], pk2(a4.x, a4.y), va[h]);
                    ffma2(acc2[i][h], pk2(a4.z, a4.w), vb[h]);
                }
            }
        }
        {   // tail m = 48 (lo half only)
            float vt[3];
            #pragma unroll
            for (int h = 0; h < 3; ++h) vt[h] = sm[OC + 48 * RS + h * HD + tj];
            #pragma unroll
            for (int i = 0; i < 7; ++i) {
                const int n = tn + 8 * i;
                #pragma unroll
                for (int h = 0; h < 3; ++h) {
                    const float at = sm[OD + h * (NTOK * ATS) + n * ATS + 48];
                    ffma2(acc2[i][h], pk2(at, 0.f), pk2(vt[h], 0.f));
                }
            }
        }
        __syncthreads();   // all attn reads done -> OD free for proj staging; OA free
        #pragma unroll
        for (int i = 0; i < 7; ++i) {
            const int n = tn + 8 * i;
            if (n < NTOK) {
                #pragma unroll
                for (int h = 0; h < 3; ++h) {
                    float lo, hi; upk2(acc2[i][h], lo, hi);
                    sm[OA + n * RS + h * HD + tj] = lo + hi;
                }
            }
        }
    }

    // ---- prestage proj weight chunk 0 -> OD buf0 (over dead attn) ----
    for (int i2 = t; i2 < 96 * 32; i2 += THREADS) {
        const int j = i2 >> 5, cc = i2 & 31;
        sm[OD + cc * QWS + j] = proj_w[j * CH + cc];
    }
    __syncthreads();

    // ================= proj GEMM (reads A, ping-pong tiles in OD, stores gmem) ==
    {
        u64 accp[7]; float accs[7];
        {
            u64 b2 = pk2(proj_b[2 * tj], proj_b[2 * tj + 1]);
            const float bs = proj_b[64 + tj];
            #pragma unroll
            for (int i = 0; i < 7; ++i) { accp[i] = b2; accs[i] = bs; }
        }
        for (int ch = 0; ch < 3; ++ch) {
            if (ch < 2) {
                const int nb = OD + ((ch + 1) & 1) * QB;
                for (int i2 = t; i2 < 96 * 32; i2 += THREADS) {
                    const int j = i2 >> 5, cc = i2 & 31;
                    sm[nb + cc * QWS + j] = proj_w[j * CH + (ch + 1) * 32 + cc];
                }
            }
            const int cb = OD + (ch & 1) * QB;
            #pragma unroll 2
            for (int cq = 0; cq < 8; ++cq) {
                float4 a4[7];
                #pragma unroll
                for (int i = 0; i < 7; ++i)
                    a4[i] = *(const float4*)&sm[OA + (tn + 8 * i) * RS + ch * 32 + cq * 4];
                const float* wb = sm + cb + (cq * 4) * QWS;
                #pragma unroll
                for (int q = 0; q < 4; ++q) {
                    u64 w2 = *(const u64*)(wb + q * QWS + 2 * tj);
                    float ws = wb[q * QWS + 64 + tj];
                    #pragma unroll
                    for (int i = 0; i < 7; ++i) {
                        const float av = (q == 0) ? a4[i].x : (q == 1) ? a4[i].y
                                       : (q == 2) ? a4[i].z : a4[i].w;
                        ffma2(accp[i], pk2(av, av), w2);
                        accs[i] += av * ws;
                    }
                }
            }
            if (ch < 2) __syncthreads();
        }
        #pragma unroll
        for (int i = 0; i < 7; ++i) {
            const int n = tn + 8 * i;
            if (n < NTOK) {
                float lo, hi; upk2(accp[i], lo, hi);
                *(float2*)(out + rowoff[n] + 2 * tj) = make_float2(lo, hi);
                out[rowoff[n] + 64 + tj] = accs[i];
            }
        }
    }
}

extern "C" void kernel_launch(void* const* d_in, const int* in_sizes, int n_in,
                              void* d_out, int out_size)
{
    (void)in_sizes; (void)n_in; (void)out_size;
    const float* query  = (const float*)d_in[0];
    const float* skipq  = (const float*)d_in[1];
    const float* qkv_w  = (const float*)d_in[2];
    const float* qkv_b  = (const float*)d_in[3];
    const float* skip_w = (const float*)d_in[4];
    const float* skip_b = (const float*)d_in[5];
    const float* proj_w = (const float*)d_in[6];
    const float* proj_b = (const float*)d_in[7];
    const float* btab   = (const float*)d_in[8];
    float* out = (float*)d_out;

    cudaFuncSetAttribute(swin_msa_kernel,
                         cudaFuncAttributeMaxDynamicSharedMemorySize, SMEM_BYTES);

    swin_msa_kernel<<<4 * 1024, THREADS, SMEM_BYTES>>>(
        query, skipq, qkv_w, qkv_b, skip_w, skip_b, proj_w, proj_b, btab, out);
}